// round 1
// baseline (speedup 1.0000x reference)
#include <cuda_runtime.h>
#include <math.h>

// Problem constants (fixed shapes from reference)
#define BATCH 4096
#define KDIM  2048   // DIN
#define NDIM  2048   // DOUT
#define DEPTH 16

// Batch-independent probs buffer (no allocation allowed -> device global)
__device__ float g_probs[NDIM];

// probs[j] = (prod_{d,g} cos(W[d, j, g]))^2 / DIN
// W layout: [DEPTH, DIN, DOUT] row-major; element [d, j, g] at ((d*KDIM + j)*NDIM + g)
__global__ void probs_kernel(const float* __restrict__ W) {
    int j = blockIdx.x * blockDim.x + threadIdx.x;
    if (j >= NDIM) return;
    float p = 1.0f;
#pragma unroll
    for (int d = 0; d < DEPTH; ++d) {
        const float* base = W + ((size_t)d * KDIM + j) * NDIM;
        p *= cosf(base[0]);
        p *= cosf(base[1]);
        p *= cosf(base[2]);
    }
    g_probs[j] = (p * p) * (1.0f / (float)KDIM);
}

// Fused GEMM + bias + probs + tanh
// out[b, n] = tanh( sum_k x[b,k] * Wc[k,n] + bias[n] + probs[n] )
#define BM 128
#define BN 128
#define BK 16
#define TM 8
#define TN 8

__global__ __launch_bounds__(256, 2) void gemm_tanh_kernel(
    const float* __restrict__ A,     // x       [BATCH, KDIM]
    const float* __restrict__ Wc,    // weights [KDIM, NDIM]
    const float* __restrict__ bias,  // [NDIM]
    float* __restrict__ out)         // [BATCH, NDIM]
{
    __shared__ float As[BK][BM];   // A tile stored transposed: As[k][m]
    __shared__ float Bs[BK][BN];

    const int bm = blockIdx.y * BM;
    const int bn = blockIdx.x * BN;
    const int tid = (int)threadIdx.x;
    const int tx = tid & 15;   // 0..15 -> n direction
    const int ty = tid >> 4;   // 0..15 -> m direction

    float acc[TM][TN];
#pragma unroll
    for (int i = 0; i < TM; ++i)
#pragma unroll
        for (int j = 0; j < TN; ++j) acc[i][j] = 0.0f;

    for (int k0 = 0; k0 < KDIM; k0 += BK) {
        // --- load A tile (BM x BK = 128x16 floats = 512 float4), transpose into As ---
        // f in [0,512): r = f>>2 (row 0..127), c = (f&3)*4 (col group)
#pragma unroll
        for (int i = 0; i < 2; ++i) {
            int f = tid + i * 256;
            int r = f >> 2;
            int c = (f & 3) << 2;
            float4 v = *(const float4*)(A + (size_t)(bm + r) * KDIM + k0 + c);
            As[c + 0][r] = v.x;
            As[c + 1][r] = v.y;
            As[c + 2][r] = v.z;
            As[c + 3][r] = v.w;
        }
        // --- load B tile (BK x BN = 16x128 floats = 512 float4), direct ---
#pragma unroll
        for (int i = 0; i < 2; ++i) {
            int f = tid + i * 256;
            int r = f >> 5;          // 0..15
            int c = (f & 31) << 2;   // 0..124
            *(float4*)(&Bs[r][c]) =
                *(const float4*)(Wc + (size_t)(k0 + r) * NDIM + bn + c);
        }
        __syncthreads();

#pragma unroll
        for (int kk = 0; kk < BK; ++kk) {
            float a[TM], b[TN];
            // vectorized smem reads (float4 pairs)
            float4 a0 = *(const float4*)(&As[kk][ty * TM]);
            float4 a1 = *(const float4*)(&As[kk][ty * TM + 4]);
            float4 b0 = *(const float4*)(&Bs[kk][tx * TN]);
            float4 b1 = *(const float4*)(&Bs[kk][tx * TN + 4]);
            a[0] = a0.x; a[1] = a0.y; a[2] = a0.z; a[3] = a0.w;
            a[4] = a1.x; a[5] = a1.y; a[6] = a1.z; a[7] = a1.w;
            b[0] = b0.x; b[1] = b0.y; b[2] = b0.z; b[3] = b0.w;
            b[4] = b1.x; b[5] = b1.y; b[6] = b1.z; b[7] = b1.w;
#pragma unroll
            for (int i = 0; i < TM; ++i)
#pragma unroll
                for (int j = 0; j < TN; ++j)
                    acc[i][j] = fmaf(a[i], b[j], acc[i][j]);
        }
        __syncthreads();
    }

    // --- epilogue: + bias + probs, tanh ---
    float badd[TN];
#pragma unroll
    for (int j = 0; j < TN; ++j) {
        int col = bn + tx * TN + j;
        badd[j] = bias[col] + g_probs[col];
    }
#pragma unroll
    for (int i = 0; i < TM; ++i) {
        int row = bm + ty * TM + i;
        float* orow = out + (size_t)row * NDIM + bn + tx * TN;
#pragma unroll
        for (int j = 0; j < TN; ++j) {
            orow[j] = tanhf(acc[i][j] + badd[j]);
        }
    }
}

extern "C" void kernel_launch(void* const* d_in, const int* in_sizes, int n_in,
                              void* d_out, int out_size) {
    (void)in_sizes; (void)n_in; (void)out_size;
    const float* x    = (const float*)d_in[0];  // [4096, 2048]
    const float* aw   = (const float*)d_in[1];  // [16, 2048, 2048]
    const float* cw   = (const float*)d_in[2];  // [2048, 2048]
    const float* cb   = (const float*)d_in[3];  // [2048]
    float* out = (float*)d_out;                 // [4096, 2048]

    probs_kernel<<<NDIM / 256, 256>>>(aw);

    dim3 grid(NDIM / BN, BATCH / BM);
    gemm_tanh_kernel<<<grid, 256>>>(x, cw, cb, out);
}

// round 2
// speedup vs baseline: 2.2977x; 2.2977x over previous
#include <cuda_runtime.h>
#include <cuda_bf16.h>
#include <math.h>
#include <stdint.h>

#define BATCH 4096
#define KDIM  2048
#define NDIM  2048
#define DEPTH 16

// ---------------- device scratch (no allocation allowed) ----------------
__device__ __nv_bfloat16 g_Ahi[(size_t)BATCH * KDIM];
__device__ __nv_bfloat16 g_Alo[(size_t)BATCH * KDIM];
__device__ __nv_bfloat16 g_Bhi[(size_t)KDIM * NDIM];
__device__ __nv_bfloat16 g_Blo[(size_t)KDIM * NDIM];
__device__ float g_padd[NDIM];   // bias + probs, fused

// ---------------- probs + bias ----------------
// probs[j] = (prod_{d,g} cos(W[d,j,g]))^2 / DIN   (uniform state is invariant
// under the rotation's sin terms; only the cos product survives)
__global__ void probs_kernel(const float* __restrict__ W,
                             const float* __restrict__ bias) {
    int j = blockIdx.x * blockDim.x + threadIdx.x;
    if (j >= NDIM) return;
    float p = 1.0f;
#pragma unroll
    for (int d = 0; d < DEPTH; ++d) {
        const float* base = W + ((size_t)d * KDIM + j) * NDIM;
        p *= cosf(base[0]);
        p *= cosf(base[1]);
        p *= cosf(base[2]);
    }
    g_padd[j] = bias[j] + (p * p) * (1.0f / (float)KDIM);
}

// ---------------- fp32 -> bf16 hi/lo split ----------------
__global__ void split_kernel(const float* __restrict__ src,
                             __nv_bfloat16* __restrict__ hi,
                             __nv_bfloat16* __restrict__ lo) {
    int i = blockIdx.x * blockDim.x + threadIdx.x;   // one float4 per thread
    float4 v = ((const float4*)src)[i];
    __nv_bfloat16 h0 = __float2bfloat16_rn(v.x);
    __nv_bfloat16 h1 = __float2bfloat16_rn(v.y);
    __nv_bfloat16 h2 = __float2bfloat16_rn(v.z);
    __nv_bfloat16 h3 = __float2bfloat16_rn(v.w);
    __nv_bfloat16 l0 = __float2bfloat16_rn(v.x - __bfloat162float(h0));
    __nv_bfloat16 l1 = __float2bfloat16_rn(v.y - __bfloat162float(h1));
    __nv_bfloat16 l2 = __float2bfloat16_rn(v.z - __bfloat162float(h2));
    __nv_bfloat16 l3 = __float2bfloat16_rn(v.w - __bfloat162float(h3));
    __nv_bfloat162* hp = (__nv_bfloat162*)(hi + 4 * (size_t)i);
    __nv_bfloat162* lp = (__nv_bfloat162*)(lo + 4 * (size_t)i);
    hp[0] = __nv_bfloat162(h0, h1);
    hp[1] = __nv_bfloat162(h2, h3);
    lp[0] = __nv_bfloat162(l0, l1);
    lp[1] = __nv_bfloat162(l2, l3);
}

// ---------------- tensor-core GEMM + tanh ----------------
// out = tanh( Ahi*Bhi + Ahi*Blo + Alo*Bhi + padd )
#define BM 128
#define BN 128
#define BK 32
#define NK (KDIM / BK)       // 64

// padded smem rows for conflict-free ldmatrix (16B-chunk strides 5 and 17)
#define ROWA_B 80            // 32 bf16 -> 64B, pad to 80B (5 chunks)
#define ROWB_B 272           // 128 bf16 -> 256B, pad to 272B (17 chunks)
#define AHI_OFF 0
#define ALO_OFF (128 * ROWA_B)                 // 10240
#define BHI_OFF (2 * 128 * ROWA_B)             // 20480
#define BLO_OFF (BHI_OFF + 32 * ROWB_B)        // 29184
#define STAGE_B (BHI_OFF + 2 * 32 * ROWB_B)    // 37888
#define SMEM_TOTAL (2 * STAGE_B)               // 75776

__device__ __forceinline__ void cp16(uint32_t dst, const void* src) {
    asm volatile("cp.async.cg.shared.global [%0], [%1], 16;\n" ::"r"(dst), "l"(src));
}
#define LDSM4(R, ADDR)                                                          \
    asm volatile("ldmatrix.sync.aligned.m8n8.x4.shared.b16 {%0,%1,%2,%3}, [%4];" \
                 : "=r"(R[0]), "=r"(R[1]), "=r"(R[2]), "=r"(R[3]) : "r"(ADDR))
#define LDSM4T(R, ADDR)                                                               \
    asm volatile("ldmatrix.sync.aligned.m8n8.x4.trans.shared.b16 {%0,%1,%2,%3}, [%4];" \
                 : "=r"(R[0]), "=r"(R[1]), "=r"(R[2]), "=r"(R[3]) : "r"(ADDR))
#define MMA(C, A, B0, B1)                                                       \
    asm volatile("mma.sync.aligned.m16n8k16.row.col.f32.bf16.bf16.f32 "          \
                 "{%0,%1,%2,%3},{%4,%5,%6,%7},{%8,%9},{%0,%1,%2,%3};"            \
                 : "+f"(C[0]), "+f"(C[1]), "+f"(C[2]), "+f"(C[3])                \
                 : "r"(A[0]), "r"(A[1]), "r"(A[2]), "r"(A[3]), "r"(B0), "r"(B1))

__global__ __launch_bounds__(256, 1) void gemm_tanh_kernel(float* __restrict__ out) {
    extern __shared__ char smem[];
    const uint32_t sbase = (uint32_t)__cvta_generic_to_shared(smem);

    const int tid  = threadIdx.x;
    const int lane = tid & 31;
    const int wid  = tid >> 5;
    const int wm = (wid & 1) * 64;    // warp m offset within tile
    const int wn = (wid >> 1) * 32;   // warp n offset within tile
    const int bm = blockIdx.y * BM;
    const int bn = blockIdx.x * BN;

    // prefetch thread mapping (two 16B chunks per matrix per thread)
    const int fa0r = tid >> 2, fa0c = tid & 3;
    const int fa1r = (tid + 256) >> 2, fa1c = fa0c;         // (tid+256)&3 == tid&3
    const int fb0r = tid >> 4, fb0c = tid & 15;
    const int fb1r = (tid + 256) >> 4, fb1c = fb0c;

    const __nv_bfloat16* Ah = g_Ahi + (size_t)bm * KDIM;
    const __nv_bfloat16* Al = g_Alo + (size_t)bm * KDIM;
    const __nv_bfloat16* Bh = g_Bhi + bn;
    const __nv_bfloat16* Bl = g_Blo + bn;

    float acc[4][4][4];
#pragma unroll
    for (int i = 0; i < 4; ++i)
#pragma unroll
        for (int j = 0; j < 4; ++j)
#pragma unroll
            for (int k = 0; k < 4; ++k) acc[i][j][k] = 0.0f;

    // ldmatrix source addresses (byte offsets within a stage)
    const int r16 = lane & 15, h4 = lane >> 4;
    // A: row = wm + mi*16 + r16, 16B chunk = h4 (8 cols), + k16*2 bytes
    const uint32_t a_base = (uint32_t)((wm + r16) * ROWA_B + h4 * 16);
    // B: row = k16 + r16, col = wn + nh*16 + 8*h4
    const uint32_t b_base = (uint32_t)(r16 * ROWB_B + (wn + 8 * h4) * 2);

    auto load_stage = [&](int s, int kt) {
        const uint32_t st = sbase + s * STAGE_B;
        const int k0 = kt * BK;
        cp16(st + AHI_OFF + fa0r * ROWA_B + fa0c * 16, Ah + (size_t)fa0r * KDIM + k0 + fa0c * 8);
        cp16(st + AHI_OFF + fa1r * ROWA_B + fa1c * 16, Ah + (size_t)fa1r * KDIM + k0 + fa1c * 8);
        cp16(st + ALO_OFF + fa0r * ROWA_B + fa0c * 16, Al + (size_t)fa0r * KDIM + k0 + fa0c * 8);
        cp16(st + ALO_OFF + fa1r * ROWA_B + fa1c * 16, Al + (size_t)fa1r * KDIM + k0 + fa1c * 8);
        cp16(st + BHI_OFF + fb0r * ROWB_B + fb0c * 16, Bh + (size_t)(k0 + fb0r) * NDIM + fb0c * 8);
        cp16(st + BHI_OFF + fb1r * ROWB_B + fb1c * 16, Bh + (size_t)(k0 + fb1r) * NDIM + fb1c * 8);
        cp16(st + BLO_OFF + fb0r * ROWB_B + fb0c * 16, Bl + (size_t)(k0 + fb0r) * NDIM + fb0c * 8);
        cp16(st + BLO_OFF + fb1r * ROWB_B + fb1c * 16, Bl + (size_t)(k0 + fb1r) * NDIM + fb1c * 8);
    };

    load_stage(0, 0);
    asm volatile("cp.async.commit_group;\n");

    for (int kt = 0; kt < NK; ++kt) {
        if (kt + 1 < NK) {
            load_stage((kt + 1) & 1, kt + 1);
            asm volatile("cp.async.commit_group;\n");
            asm volatile("cp.async.wait_group 1;\n");
        } else {
            asm volatile("cp.async.wait_group 0;\n");
        }
        __syncthreads();

        const uint32_t st = sbase + (kt & 1) * STAGE_B;
#pragma unroll
        for (int k16 = 0; k16 < BK; k16 += 16) {
            uint32_t ah[4][4], al[4][4], bh[2][4], bl[2][4];
#pragma unroll
            for (int mi = 0; mi < 4; ++mi) {
                uint32_t ad = st + a_base + mi * 16 * ROWA_B + k16 * 2;
                LDSM4(ah[mi], ad + AHI_OFF);
                LDSM4(al[mi], ad + ALO_OFF);
            }
#pragma unroll
            for (int nh = 0; nh < 2; ++nh) {
                uint32_t bd = st + b_base + k16 * ROWB_B + nh * 32;
                LDSM4T(bh[nh], bd + BHI_OFF);
                LDSM4T(bl[nh], bd + BLO_OFF);
            }
#pragma unroll
            for (int mi = 0; mi < 4; ++mi)
#pragma unroll
                for (int ni = 0; ni < 4; ++ni) {
                    const int nh = ni >> 1, o = (ni & 1) * 2;
                    MMA(acc[mi][ni], ah[mi], bh[nh][o], bh[nh][o + 1]);
                    MMA(acc[mi][ni], ah[mi], bl[nh][o], bl[nh][o + 1]);
                    MMA(acc[mi][ni], al[mi], bh[nh][o], bh[nh][o + 1]);
                }
        }
        __syncthreads();
    }

    // ---------------- epilogue ----------------
    const int g = lane >> 2, tig = lane & 3;
#pragma unroll
    for (int mi = 0; mi < 4; ++mi) {
#pragma unroll
        for (int ni = 0; ni < 4; ++ni) {
            const int col = bn + wn + ni * 8 + 2 * tig;
            const float add0 = g_padd[col];
            const float add1 = g_padd[col + 1];
            const int row0 = bm + wm + mi * 16 + g;
            float2 v0, v1;
            v0.x = tanhf(acc[mi][ni][0] + add0);
            v0.y = tanhf(acc[mi][ni][1] + add1);
            v1.x = tanhf(acc[mi][ni][2] + add0);
            v1.y = tanhf(acc[mi][ni][3] + add1);
            *(float2*)(out + (size_t)row0 * NDIM + col) = v0;
            *(float2*)(out + (size_t)(row0 + 8) * NDIM + col) = v1;
        }
    }
}

// ---------------- launch ----------------
extern "C" void kernel_launch(void* const* d_in, const int* in_sizes, int n_in,
                              void* d_out, int out_size) {
    (void)in_sizes; (void)n_in; (void)out_size;
    const float* x  = (const float*)d_in[0];
    const float* aw = (const float*)d_in[1];
    const float* cw = (const float*)d_in[2];
    const float* cb = (const float*)d_in[3];
    float* out = (float*)d_out;

    static bool attr_done = false;
    if (!attr_done) {
        cudaFuncSetAttribute(gemm_tanh_kernel,
                             cudaFuncAttributeMaxDynamicSharedMemorySize, SMEM_TOTAL);
        attr_done = true;
    }

    __nv_bfloat16 *ahi, *alo, *bhi, *blo;
    cudaGetSymbolAddress((void**)&ahi, g_Ahi);
    cudaGetSymbolAddress((void**)&alo, g_Alo);
    cudaGetSymbolAddress((void**)&bhi, g_Bhi);
    cudaGetSymbolAddress((void**)&blo, g_Blo);

    split_kernel<<<(BATCH * KDIM / 4) / 256, 256>>>(x, ahi, alo);
    split_kernel<<<(KDIM * NDIM / 4) / 256, 256>>>(cw, bhi, blo);
    probs_kernel<<<NDIM / 256, 256>>>(aw, cb);

    dim3 grid(NDIM / BN, BATCH / BM);
    gemm_tanh_kernel<<<grid, 256, SMEM_TOTAL>>>(out);
}

// round 4
// speedup vs baseline: 2.5510x; 1.1103x over previous
#include <cuda_runtime.h>
#include <cuda_bf16.h>
#include <math.h>
#include <stdint.h>

#define BATCH 4096
#define KDIM  2048
#define NDIM  2048
#define DEPTH 16

// ---------------- device scratch (no allocation allowed) ----------------
__device__ __nv_bfloat16 g_Ahi[(size_t)BATCH * KDIM];
__device__ __nv_bfloat16 g_Alo[(size_t)BATCH * KDIM];
__device__ __nv_bfloat16 g_Bhi[(size_t)KDIM * NDIM];
__device__ __nv_bfloat16 g_Blo[(size_t)KDIM * NDIM];
__device__ float g_padd[NDIM];   // bias + probs, fused

// ---------------- probs + bias ----------------
// probs[j] = (prod_{d,g} cos(W[d,j,g]))^2 / DIN  (uniform state kills the sin terms)
__global__ void probs_kernel(const float* __restrict__ W,
                             const float* __restrict__ bias) {
    int j = blockIdx.x * blockDim.x + threadIdx.x;
    if (j >= NDIM) return;
    float p = 1.0f;
#pragma unroll
    for (int d = 0; d < DEPTH; ++d) {
        const float* base = W + ((size_t)d * KDIM + j) * NDIM;
        p *= cosf(base[0]);
        p *= cosf(base[1]);
        p *= cosf(base[2]);
    }
    g_padd[j] = bias[j] + (p * p) * (1.0f / (float)KDIM);
}

// ---------------- fp32 -> bf16 hi/lo split ----------------
__global__ void split_kernel(const float* __restrict__ src,
                             __nv_bfloat16* __restrict__ hi,
                             __nv_bfloat16* __restrict__ lo) {
    int i = blockIdx.x * blockDim.x + threadIdx.x;   // one float4 per thread
    float4 v = ((const float4*)src)[i];
    __nv_bfloat16 h0 = __float2bfloat16_rn(v.x), h1 = __float2bfloat16_rn(v.y);
    __nv_bfloat16 h2 = __float2bfloat16_rn(v.z), h3 = __float2bfloat16_rn(v.w);
    __nv_bfloat16 l0 = __float2bfloat16_rn(v.x - __bfloat162float(h0));
    __nv_bfloat16 l1 = __float2bfloat16_rn(v.y - __bfloat162float(h1));
    __nv_bfloat16 l2 = __float2bfloat16_rn(v.z - __bfloat162float(h2));
    __nv_bfloat16 l3 = __float2bfloat16_rn(v.w - __bfloat162float(h3));
    __nv_bfloat162* hp = (__nv_bfloat162*)(hi + 4 * (size_t)i);
    __nv_bfloat162* lp = (__nv_bfloat162*)(lo + 4 * (size_t)i);
    hp[0] = __nv_bfloat162(h0, h1); hp[1] = __nv_bfloat162(h2, h3);
    lp[0] = __nv_bfloat162(l0, l1); lp[1] = __nv_bfloat162(l2, l3);
}

// ---------------- tensor-core GEMM + tanh ----------------
// out = tanh( Ahi*Bhi + Ahi*Blo + Alo*Bhi + padd )
#define BM 128
#define BN 256
#define BK 32
#define NK (KDIM / BK)       // 64
#define NSTAGE 3

// padded smem rows: 16B-chunk strides 5 (A) and 33 (B) -> conflict-free ldmatrix
#define ROWA_B 80                            // 32 bf16 = 64B data, pad to 80B
#define ROWB_B 528                           // 256 bf16 = 512B data, pad to 528B
#define AHI_OFF 0
#define ALO_OFF (128 * ROWA_B)               // 10240
#define BHI_OFF (2 * 128 * ROWA_B)           // 20480
#define BLO_OFF (BHI_OFF + 32 * ROWB_B)      // 37376
#define STAGE_B (BHI_OFF + 2 * 32 * ROWB_B)  // 54272
#define SMEM_TOTAL (NSTAGE * STAGE_B)        // 162816

__device__ __forceinline__ void cp16(uint32_t dst, const void* src) {
    asm volatile("cp.async.cg.shared.global [%0], [%1], 16;\n" ::"r"(dst), "l"(src));
}
#define LDSM4(R, ADDR)                                                           \
    asm volatile("ldmatrix.sync.aligned.m8n8.x4.shared.b16 {%0,%1,%2,%3}, [%4];" \
                 : "=r"(R[0]), "=r"(R[1]), "=r"(R[2]), "=r"(R[3]) : "r"(ADDR))
#define LDSM4T(R, ADDR)                                                                \
    asm volatile("ldmatrix.sync.aligned.m8n8.x4.trans.shared.b16 {%0,%1,%2,%3}, [%4];" \
                 : "=r"(R[0]), "=r"(R[1]), "=r"(R[2]), "=r"(R[3]) : "r"(ADDR))
#define MMA(C, A, B0, B1)                                               \
    asm volatile("mma.sync.aligned.m16n8k16.row.col.f32.bf16.bf16.f32 " \
                 "{%0,%1,%2,%3},{%4,%5,%6,%7},{%8,%9},{%0,%1,%2,%3};"   \
                 : "+f"(C[0]), "+f"(C[1]), "+f"(C[2]), "+f"(C[3])       \
                 : "r"(A[0]), "r"(A[1]), "r"(A[2]), "r"(A[3]), "r"(B0), "r"(B1))

__global__ __launch_bounds__(256, 1) void gemm_tanh_kernel(float* __restrict__ out) {
    extern __shared__ char smem[];
    const uint32_t sbase = (uint32_t)__cvta_generic_to_shared(smem);

    const int tid  = threadIdx.x;
    const int lane = tid & 31;
    const int wid  = tid >> 5;
    const int wm = (wid & 1) * 64;    // 2 warps over M
    const int wn = (wid >> 1) * 64;   // 4 warps over N
    const int bm = blockIdx.y * BM;
    const int bn = blockIdx.x * BN;

    const __nv_bfloat16* Ah = g_Ahi + (size_t)bm * KDIM;
    const __nv_bfloat16* Al = g_Alo + (size_t)bm * KDIM;
    const __nv_bfloat16* Bh = g_Bhi + bn;
    const __nv_bfloat16* Bl = g_Blo + bn;

    float acc[4][8][4];
#pragma unroll
    for (int i = 0; i < 4; ++i)
#pragma unroll
        for (int j = 0; j < 8; ++j)
#pragma unroll
            for (int k = 0; k < 4; ++k) acc[i][j][k] = 0.0f;

    // ldmatrix base addresses (byte offsets within a stage)
    const int r16 = lane & 15, h4 = lane >> 4;
    const uint32_t a_base = (uint32_t)((wm + r16) * ROWA_B + h4 * 16);
    const uint32_t b_base = (uint32_t)(r16 * ROWB_B + (wn + 8 * h4) * 2);

    auto load_stage = [&](int s, int kt) {
        const uint32_t st = sbase + s * STAGE_B;
        const int k0 = kt * BK;
        // A hi/lo: 128 rows x 4 chunks of 16B (512 chunks, 2 per thread)
#pragma unroll
        for (int i = 0; i < 2; ++i) {
            const int f = tid + i * 256;
            const int r = f >> 2, c = f & 3;
            const uint32_t so = (uint32_t)(r * ROWA_B + c * 16);
            const size_t go = (size_t)r * KDIM + k0 + c * 8;
            cp16(st + AHI_OFF + so, Ah + go);
            cp16(st + ALO_OFF + so, Al + go);
        }
        // B hi/lo: 32 rows x 32 chunks of 16B (1024 chunks, 4 per thread)
#pragma unroll
        for (int i = 0; i < 4; ++i) {
            const int f = tid + i * 256;
            const int r = f >> 5, c = f & 31;
            const uint32_t so = (uint32_t)(r * ROWB_B + c * 16);
            const size_t go = (size_t)(k0 + r) * NDIM + c * 8;
            cp16(st + BHI_OFF + so, Bh + go);
            cp16(st + BLO_OFF + so, Bl + go);
        }
    };

    load_stage(0, 0);
    asm volatile("cp.async.commit_group;\n");
    load_stage(1, 1);
    asm volatile("cp.async.commit_group;\n");

    int s_cur = 0;
    for (int kt = 0; kt < NK; ++kt) {
        if (kt + 1 < NK) asm volatile("cp.async.wait_group 1;\n");
        else             asm volatile("cp.async.wait_group 0;\n");
        __syncthreads();

        if (kt + 2 < NK) {
            int s_next = s_cur + 2;
            if (s_next >= NSTAGE) s_next -= NSTAGE;
            load_stage(s_next, kt + 2);
            asm volatile("cp.async.commit_group;\n");
        }

        const uint32_t st = sbase + s_cur * STAGE_B;
#pragma unroll
        for (int k16 = 0; k16 < BK; k16 += 16) {
            uint32_t ah[4][4], al[4][4];
#pragma unroll
            for (int mi = 0; mi < 4; ++mi) {
                const uint32_t ad = st + a_base + mi * 16 * ROWA_B + k16 * 2;
                LDSM4(ah[mi], ad + AHI_OFF);
                LDSM4(al[mi], ad + ALO_OFF);
            }
#pragma unroll
            for (int n16 = 0; n16 < 4; ++n16) {   // 16-col sub-tiles of the 64-col warp tile
                uint32_t bh[4], bl[4];
                const uint32_t bd = st + b_base + k16 * ROWB_B + n16 * 32;
                LDSM4T(bh, bd + BHI_OFF);
                LDSM4T(bl, bd + BLO_OFF);
#pragma unroll
                for (int mi = 0; mi < 4; ++mi) {
                    MMA(acc[mi][2 * n16 + 0], ah[mi], bh[0], bh[1]);
                    MMA(acc[mi][2 * n16 + 1], ah[mi], bh[2], bh[3]);
                    MMA(acc[mi][2 * n16 + 0], ah[mi], bl[0], bl[1]);
                    MMA(acc[mi][2 * n16 + 1], ah[mi], bl[2], bl[3]);
                    MMA(acc[mi][2 * n16 + 0], al[mi], bh[0], bh[1]);
                    MMA(acc[mi][2 * n16 + 1], al[mi], bh[2], bh[3]);
                }
            }
        }
        __syncthreads();
        if (++s_cur == NSTAGE) s_cur = 0;
    }

    // ---------------- epilogue: + (bias+probs), tanh ----------------
    const int g = lane >> 2, tig = lane & 3;
    float2 badd[8];
#pragma unroll
    for (int ni = 0; ni < 8; ++ni)
        badd[ni] = *(const float2*)(g_padd + bn + wn + ni * 8 + 2 * tig);
#pragma unroll
    for (int mi = 0; mi < 4; ++mi) {
        const int row0 = bm + wm + mi * 16 + g;
#pragma unroll
        for (int ni = 0; ni < 8; ++ni) {
            const int col = bn + wn + ni * 8 + 2 * tig;
            float2 v0, v1;
            v0.x = tanhf(acc[mi][ni][0] + badd[ni].x);
            v0.y = tanhf(acc[mi][ni][1] + badd[ni].y);
            v1.x = tanhf(acc[mi][ni][2] + badd[ni].x);
            v1.y = tanhf(acc[mi][ni][3] + badd[ni].y);
            *(float2*)(out + (size_t)row0 * NDIM + col) = v0;
            *(float2*)(out + (size_t)(row0 + 8) * NDIM + col) = v1;
        }
    }
}

// ---------------- launch ----------------
extern "C" void kernel_launch(void* const* d_in, const int* in_sizes, int n_in,
                              void* d_out, int out_size) {
    (void)in_sizes; (void)n_in; (void)out_size;
    const float* x  = (const float*)d_in[0];
    const float* aw = (const float*)d_in[1];
    const float* cw = (const float*)d_in[2];
    const float* cb = (const float*)d_in[3];
    float* out = (float*)d_out;

    static bool attr_done = false;
    if (!attr_done) {
        cudaFuncSetAttribute(gemm_tanh_kernel,
                             cudaFuncAttributeMaxDynamicSharedMemorySize, SMEM_TOTAL);
        attr_done = true;
    }

    __nv_bfloat16 *ahi, *alo, *bhi, *blo;
    cudaGetSymbolAddress((void**)&ahi, g_Ahi);
    cudaGetSymbolAddress((void**)&alo, g_Alo);
    cudaGetSymbolAddress((void**)&bhi, g_Bhi);
    cudaGetSymbolAddress((void**)&blo, g_Blo);

    split_kernel<<<(BATCH * KDIM / 4) / 256, 256>>>(x, ahi, alo);
    split_kernel<<<(KDIM * NDIM / 4) / 256, 256>>>(cw, bhi, blo);
    probs_kernel<<<NDIM / 256, 256>>>(aw, cb);

    dim3 grid(NDIM / BN, BATCH / BM);
    gemm_tanh_kernel<<<grid, 256, SMEM_TOTAL>>>(out);
}